// round 17
// baseline (speedup 1.0000x reference)
#include <cuda_runtime.h>
#include <cuda_fp16.h>
#include <cstdint>

// ---------------------------------------------------------------------------
// CrossAttention on GB300 (sm_103a; plain compute_103 -> mma.sync fp16).
// R17: R16 (Winograd F(4x4,3x3) conv, single-fp16 GEMMs) with softmax FUSED
// into the AV kernel bit-identically (same reduction order, same __expf, same
// fp16 rounding). Conv path byte-frozen (rel_err margin is thin).
// ---------------------------------------------------------------------------

#define NB   4
#define CCH  512
#define HW   1024
#define NHD  8
#define DHEAD 128

typedef __half fp16;

// Scratch (no allocations -> __device__ globals)
__device__ fp16  g_U[(size_t)6 * 36 * 512 * 512];  // [conv][xi][co][ci]
__device__ fp16  g_V[(size_t)2 * 36 * 512 * 256];  // [inp][xi][ci][n*64+t]
__device__ fp16  g_C[(size_t)6 * 36 * 512 * 256];  // [conv][xi][co][n*64+t]
__device__ fp16  g_q1[6][NB * CCH * HW];           // kl,ql,vl,kg,qg,vg
__device__ float g_att[2][NB * NHD * 512 * 512];   // pre-softmax
__device__ fp16  g_y1[2][NB * CCH * HW];           // y_g, y_l
__device__ fp16  g_wp1[2][512 * 512];

// ============================ helpers =======================================
__device__ __forceinline__ uint32_t smem_u32(const void* p) {
    uint32_t a;
    asm("{ .reg .u64 t; cvta.to.shared.u64 t, %1; cvt.u32.u64 %0, t; }"
        : "=r"(a) : "l"(p));
    return a;
}

__device__ __forceinline__ void mma_f16(float* c, const uint32_t* a, const uint32_t* b) {
    asm volatile(
        "mma.sync.aligned.m16n8k16.row.col.f32.f16.f16.f32 "
        "{%0,%1,%2,%3}, {%4,%5,%6,%7}, {%8,%9}, {%0,%1,%2,%3};"
        : "+f"(c[0]), "+f"(c[1]), "+f"(c[2]), "+f"(c[3])
        : "r"(a[0]), "r"(a[1]), "r"(a[2]), "r"(a[3]), "r"(b[0]), "r"(b[1]));
}

#define LDSM4(r0, r1, r2, r3, addr) \
    asm volatile("ldmatrix.sync.aligned.m8n8.x4.shared.b16 {%0,%1,%2,%3}, [%4];" \
                 : "=r"(r0), "=r"(r1), "=r"(r2), "=r"(r3) : "r"(addr))

#define LDSM2T(r0, r1, addr) \
    asm volatile("ldmatrix.sync.aligned.m8n8.x2.trans.shared.b16 {%0,%1}, [%2];" \
                 : "=r"(r0), "=r"(r1) : "r"(addr))

#define CPA(dst, src, sz) \
    asm volatile("cp.async.ca.shared.global [%0], [%1], 16, %2;" \
                 :: "r"(dst), "l"(src), "r"(sz) : "memory")
#define CP_COMMIT() asm volatile("cp.async.commit_group;" ::: "memory")
#define CP_WAIT1()  asm volatile("cp.async.wait_group 1;" ::: "memory")
#define CP_WAIT0()  asm volatile("cp.async.wait_group 0;" ::: "memory")

#define STS128I(addr, u0, u1, u2, u3) \
    asm volatile("st.shared.v4.u32 [%0], {%1,%2,%3,%4};" \
                 :: "r"(addr), "r"(u0), "r"(u1), "r"(u2), "r"(u3) : "memory")

// ============================ layout consts =================================
#define ROWB 80
#define MATB (128 * ROWB)             // 10240
#define ROW2 272
#define MATB2 (32 * ROW2)             // 8704
#define STG2 (2 * MATB)               // nn stage: A B          20480
#define SM22 (2 * STG2)               // 2-stage                40960
#define STGN (MATB + MATB2)           // nt stage: A B          18944
#define SMN  (2 * STGN)               // 37888
#define SMAV (2 * STGN + 1024)        // fused av: stages + m[128] + inv[128]

#define NCOL 256                      // Winograd GEMM N (4 n * 64 tiles)

// ======================== Winograd F(4,3) transforms ========================
__global__ void wino_w(const float* __restrict__ w0, const float* __restrict__ w1,
                       const float* __restrict__ w2, const float* __restrict__ w3,
                       const float* __restrict__ w4, const float* __restrict__ w5,
                       fp16* __restrict__ U) {
    const float* ws[6] = {w0, w1, w2, w3, w4, w5};
    int conv = blockIdx.y;
    const float* w = ws[conv];
    int t = blockIdx.x * 256 + threadIdx.x;
    int co = t >> 9, ci = t & 511;
    float g[3][3];
#pragma unroll
    for (int i = 0; i < 9; ++i) g[i / 3][i % 3] = w[(size_t)t * 9 + i];
    float a[6][3];
#pragma unroll
    for (int c = 0; c < 3; ++c) {
        a[0][c] = 0.25f * g[0][c];
        a[1][c] = (-1.f / 6.f) * (g[0][c] + g[1][c] + g[2][c]);
        a[2][c] = (-1.f / 6.f) * (g[0][c] - g[1][c] + g[2][c]);
        a[3][c] = (1.f / 24.f) * g[0][c] + (1.f / 12.f) * g[1][c] + (1.f / 6.f) * g[2][c];
        a[4][c] = (1.f / 24.f) * g[0][c] - (1.f / 12.f) * g[1][c] + (1.f / 6.f) * g[2][c];
        a[5][c] = g[2][c];
    }
    float u[6][6];
#pragma unroll
    for (int r = 0; r < 6; ++r) {
        u[r][0] = 0.25f * a[r][0];
        u[r][1] = (-1.f / 6.f) * (a[r][0] + a[r][1] + a[r][2]);
        u[r][2] = (-1.f / 6.f) * (a[r][0] - a[r][1] + a[r][2]);
        u[r][3] = (1.f / 24.f) * a[r][0] + (1.f / 12.f) * a[r][1] + (1.f / 6.f) * a[r][2];
        u[r][4] = (1.f / 24.f) * a[r][0] - (1.f / 12.f) * a[r][1] + (1.f / 6.f) * a[r][2];
        u[r][5] = a[r][2];
    }
#pragma unroll
    for (int xi = 0; xi < 36; ++xi)
        U[(((size_t)conv * 36 + xi) * 512 + co) * 512 + ci] =
            __float2half_rn(u[xi / 6][xi % 6]);
}

__global__ void wino_v(const float* __restrict__ xl, const float* __restrict__ xg,
                       fp16* __restrict__ V) {
    int z = blockIdx.y;
    int inp = z >> 2, n = z & 3;
    const float* x = (inp ? xg : xl) + (size_t)n * (CCH * HW);
    int idx = blockIdx.x * 256 + threadIdx.x;
    int ci = idx >> 6, t = idx & 63;
    int ty = t >> 3, tx = t & 7;
    const float* xc = x + (size_t)ci * HW;
    int r0 = 4 * ty - 1, c0 = 4 * tx - 1;
    float d[6][6];
#pragma unroll
    for (int i = 0; i < 6; ++i)
#pragma unroll
        for (int j = 0; j < 6; ++j) {
            int rr = r0 + i, cc = c0 + j;
            d[i][j] = ((unsigned)rr < 32u && (unsigned)cc < 32u)
                          ? xc[rr * 32 + cc] : 0.f;
        }
    float e[6][6];
#pragma unroll
    for (int j = 0; j < 6; ++j) {
        e[0][j] =  4.f * d[0][j] - 5.f * d[2][j] + d[4][j];
        e[1][j] = -4.f * d[1][j] - 4.f * d[2][j] + d[3][j] + d[4][j];
        e[2][j] =  4.f * d[1][j] - 4.f * d[2][j] - d[3][j] + d[4][j];
        e[3][j] = -2.f * d[1][j] -       d[2][j] + 2.f * d[3][j] + d[4][j];
        e[4][j] =  2.f * d[1][j] -       d[2][j] - 2.f * d[3][j] + d[4][j];
        e[5][j] =  4.f * d[1][j] - 5.f * d[3][j] + d[5][j];
    }
    float v[6][6];
#pragma unroll
    for (int i = 0; i < 6; ++i) {
        v[i][0] =  4.f * e[i][0] - 5.f * e[i][2] + e[i][4];
        v[i][1] = -4.f * e[i][1] - 4.f * e[i][2] + e[i][3] + e[i][4];
        v[i][2] =  4.f * e[i][1] - 4.f * e[i][2] - e[i][3] + e[i][4];
        v[i][3] = -2.f * e[i][1] -       e[i][2] + 2.f * e[i][3] + e[i][4];
        v[i][4] =  2.f * e[i][1] -       e[i][2] - 2.f * e[i][3] + e[i][4];
        v[i][5] =  4.f * e[i][1] - 5.f * e[i][3] + e[i][5];
    }
#pragma unroll
    for (int xi = 0; xi < 36; ++xi)
        V[(((size_t)inp * 36 + xi) * 512 + ci) * NCOL + n * 64 + t] =
            __float2half_rn(v[xi / 6][xi % 6]);
}

__global__ void prep_wp(const float* __restrict__ wp1, const float* __restrict__ wp2,
                        fp16* __restrict__ wo) {
    int pidx = blockIdx.y;
    const float* w = pidx ? wp2 : wp1;
    int idx = blockIdx.x * 256 + threadIdx.x;
    wo[(size_t)pidx * 512 * 512 + idx] = __float2half_rn(w[idx]);
}

// ======================= mma inner phases (single A) ========================
__device__ __forceinline__ void mma_phase_nn(uint32_t st, uint32_t a_base,
                                             uint32_t b_base, float acc[4][4][4]) {
    uint32_t sA = st, sB = st + MATB;
#pragma unroll
    for (int kt = 0; kt < 2; ++kt) {
        uint32_t aa[4][4], bb[4][2];
#pragma unroll
        for (int mt = 0; mt < 4; ++mt) {
            uint32_t ad = a_base + (uint32_t)(mt * 16 * ROWB + kt * 32);
            LDSM4(aa[mt][0], aa[mt][1], aa[mt][2], aa[mt][3], sA + ad);
        }
#pragma unroll
        for (int p = 0; p < 2; ++p) {
            uint32_t bd = b_base + (uint32_t)(p * 16 * ROWB + kt * 32);
            uint32_t r0, r1, r2, r3;
            LDSM4(r0, r1, r2, r3, sB + bd);
            bb[2 * p][0] = r0; bb[2 * p][1] = r2;
            bb[2 * p + 1][0] = r1; bb[2 * p + 1][1] = r3;
        }
#pragma unroll
        for (int mt = 0; mt < 4; ++mt)
#pragma unroll
            for (int nt = 0; nt < 4; ++nt)
                mma_f16(acc[mt][nt], aa[mt], bb[nt]);
    }
}

__device__ __forceinline__ void mma_phase_nt(uint32_t st, uint32_t a_base,
                                             uint32_t bt_base, float acc[4][4][4]) {
    uint32_t sA = st, sB = st + MATB;
#pragma unroll
    for (int kt = 0; kt < 2; ++kt) {
        uint32_t aa[4][4], bb[4][2];
#pragma unroll
        for (int mt = 0; mt < 4; ++mt) {
            uint32_t ad = a_base + (uint32_t)(mt * 16 * ROWB + kt * 32);
            LDSM4(aa[mt][0], aa[mt][1], aa[mt][2], aa[mt][3], sA + ad);
        }
#pragma unroll
        for (int nt = 0; nt < 4; ++nt) {
            uint32_t bd = bt_base + (uint32_t)(kt * 16 * ROW2 + nt * 16);
            LDSM2T(bb[nt][0], bb[nt][1], sB + bd);
        }
#pragma unroll
        for (int mt = 0; mt < 4; ++mt)
#pragma unroll
            for (int nt = 0; nt < 4; ++nt)
                mma_f16(acc[mt][nt], aa[mt], bb[nt]);
    }
}

// ============ Winograd-domain GEMM: C[xi] = U[xi] x V[xi] ===================
__global__ __launch_bounds__(256, 2)
void wino_gemm(const fp16* __restrict__ U, const fp16* __restrict__ V,
               fp16* __restrict__ C) {
    extern __shared__ unsigned char dsm[];
    const uint32_t sb = smem_u32(dsm);

    int tid = threadIdx.x, wid = tid >> 5, lid = tid & 31;
    int warp_m = wid >> 2, warp_n = wid & 3;
    int z = blockIdx.z;
    int conv = z / 36, xi = z % 36;
    int inp = (conv < 3) ? 0 : 1;
    int tile0 = blockIdx.x * 128, co0 = blockIdx.y * 128;
    const fp16* A = U + ((size_t)conv * 36 + xi) * 512 * 512;
    const fp16* B = V + ((size_t)inp * 36 + xi) * 512 * NCOL;
    fp16* Cb = C + ((size_t)conv * 36 + xi) * 512 * NCOL;

    float acc[4][4][4];
#pragma unroll
    for (int mt = 0; mt < 4; ++mt)
#pragma unroll
        for (int nt = 0; nt < 4; ++nt)
#pragma unroll
            for (int kk = 0; kk < 4; ++kk) acc[mt][nt][kk] = 0.f;

    int grp = lid >> 3, lr = lid & 7;
    uint32_t a_base = (uint32_t)((warp_m * 64 + (grp & 1) * 8 + lr) * ROWB + (grp >> 1) * 16);
    int l16 = lid & 15;
    uint32_t bt_base = (uint32_t)(l16 * ROW2 + warp_n * 64);

    int row = tid >> 1, half = tid & 1;
    uint32_t dstA = (uint32_t)(row * ROWB + half * 32);
    int cir = tid >> 3, seg = tid & 7;
    uint32_t dstB = (uint32_t)(cir * ROW2 + seg * 32);

    auto prefetch = [&](int ch, int st) {
        uint32_t s0b = sb + st * STGN;
        int ci0 = ch << 5;
        size_t wof = (size_t)(co0 + row) * 512 + ci0 + half * 16;
        uint32_t da = s0b + dstA;
        CPA(da,      A + wof,     16u);
        CPA(da + 16, A + wof + 8, 16u);
        size_t bof = (size_t)(ci0 + cir) * NCOL + tile0 + seg * 16;
        uint32_t db = s0b + MATB + dstB;
        CPA(db,      B + bof,     16u);
        CPA(db + 16, B + bof + 8, 16u);
    };

    prefetch(0, 0); CP_COMMIT();
    for (int ch = 0; ch < 16; ++ch) {
        if (ch + 1 < 16) { prefetch(ch + 1, (ch + 1) & 1); CP_COMMIT(); CP_WAIT1(); }
        else CP_WAIT0();
        __syncthreads();
        mma_phase_nt(sb + (ch & 1) * STGN, a_base, bt_base, acc);
        __syncthreads();
    }

#pragma unroll
    for (int mt = 0; mt < 4; ++mt) {
        int m = co0 + warp_m * 64 + mt * 16 + (lid >> 2);
#pragma unroll
        for (int nt = 0; nt < 4; ++nt) {
            int sc = tile0 + warp_n * 32 + nt * 8 + (lid & 3) * 2;
            __half2 p0 = __floats2half2_rn(acc[mt][nt][0], acc[mt][nt][1]);
            __half2 p1 = __floats2half2_rn(acc[mt][nt][2], acc[mt][nt][3]);
            *(uint32_t*)&Cb[(size_t)m * NCOL + sc] = *(uint32_t*)&p0;
            *(uint32_t*)&Cb[(size_t)(m + 8) * NCOL + sc] = *(uint32_t*)&p1;
        }
    }
}

// ================ inverse transform: Y = A^T M A -> qkv =====================
__global__ void wino_inv(const fp16* __restrict__ C, fp16* __restrict__ q1) {
    int conv = blockIdx.z, n = blockIdx.y;
    int idx = blockIdx.x * 256 + threadIdx.x;
    int co = idx >> 6, t = idx & 63;
    int ty = t >> 3, tx = t & 7;
    const size_t XSTR = (size_t)512 * NCOL;
    size_t base = (size_t)conv * 36 * XSTR + (size_t)co * NCOL + n * 64 + t;
    float m[6][6];
#pragma unroll
    for (int xi = 0; xi < 36; ++xi)
        m[xi / 6][xi % 6] = __half2float(C[base + (size_t)xi * XSTR]);
    float p[4][6];
#pragma unroll
    for (int j = 0; j < 6; ++j) {
        p[0][j] = m[0][j] + m[1][j] + m[2][j] + m[3][j] + m[4][j];
        p[1][j] = m[1][j] - m[2][j] + 2.f * m[3][j] - 2.f * m[4][j];
        p[2][j] = m[1][j] + m[2][j] + 4.f * m[3][j] + 4.f * m[4][j];
        p[3][j] = m[1][j] - m[2][j] + 8.f * m[3][j] - 8.f * m[4][j] + m[5][j];
    }
    float y[4][4];
#pragma unroll
    for (int i = 0; i < 4; ++i) {
        y[i][0] = p[i][0] + p[i][1] + p[i][2] + p[i][3] + p[i][4];
        y[i][1] = p[i][1] - p[i][2] + 2.f * p[i][3] - 2.f * p[i][4];
        y[i][2] = p[i][1] + p[i][2] + 4.f * p[i][3] + 4.f * p[i][4];
        y[i][3] = p[i][1] - p[i][2] + 8.f * p[i][3] - 8.f * p[i][4] + p[i][5];
    }
    fp16* o = q1 + ((size_t)conv * NB + n) * (CCH * HW) + (size_t)co * HW;
    int oy = 4 * ty, ox = 4 * tx;
#pragma unroll
    for (int i = 0; i < 4; ++i) {
        __half2 r0 = __floats2half2_rn(y[i][0], y[i][1]);
        __half2 r1 = __floats2half2_rn(y[i][2], y[i][3]);
        *(uint32_t*)&o[(oy + i) * 32 + ox] = *(uint32_t*)&r0;
        *(uint32_t*)&o[(oy + i) * 32 + ox + 2] = *(uint32_t*)&r1;
    }
}

// ================== QK^T: single fp16, 2-stage cp.async =====================
__global__ __launch_bounds__(256, 2)
void qk_mma_kernel(const fp16* __restrict__ qk1, float* __restrict__ att) {
    extern __shared__ unsigned char dsm[];
    const uint32_t sb = smem_u32(dsm);
    const size_t QKV_N = (size_t)NB * CCH * HW;
    const size_t ATT_N = (size_t)NB * NHD * 512 * 512;

    int tid = threadIdx.x, wid = tid >> 5, lid = tid & 31;
    int warp_m = wid >> 2, warp_n = wid & 3;
    int z = blockIdx.z, sel = z >> 5, nh = z & 31;
    int n = nh >> 3, h = nh & 7;
    int ck0 = blockIdx.x * 128, cq0 = blockIdx.y * 128;
    size_t base = (size_t)n * (CCH * HW) + h * DHEAD;
    const fp16* qb = qk1 + (sel ? 1 : 4) * QKV_N + base;
    const fp16* kb = qk1 + (sel ? 3 : 0) * QKV_N + base;

    float acc[4][4][4];
#pragma unroll
    for (int mt = 0; mt < 4; ++mt)
#pragma unroll
        for (int nt = 0; nt < 4; ++nt)
#pragma unroll
            for (int kk = 0; kk < 4; ++kk) acc[mt][nt][kk] = 0.f;

    int grp = lid >> 3, lr = lid & 7;
    uint32_t a_base = (uint32_t)((warp_m * 64 + (grp & 1) * 8 + lr) * ROWB + (grp >> 1) * 16);
    uint32_t b_base = (uint32_t)((warp_n * 32 + (grp & 1) * 8 + lr) * ROWB + (grp >> 1) * 16);

    int row = tid >> 1, half = tid & 1;
    uint32_t dstA = (uint32_t)(row * ROWB + half * 32);

    auto prefetch = [&](int ch, int st) {
        uint32_t s0b = sb + st * STG2;
        int ci0 = ch << 5;
        size_t qof = (size_t)(cq0 + row) * HW + ci0 + half * 16;
        size_t kof = (size_t)(ck0 + row) * HW + ci0 + half * 16;
        uint32_t da = s0b + dstA;
        CPA(da,      qb + qof,     16u);
        CPA(da + 16, qb + qof + 8, 16u);
        uint32_t db = s0b + MATB + dstA;
        CPA(db,      kb + kof,     16u);
        CPA(db + 16, kb + kof + 8, 16u);
    };

    prefetch(0, 0); CP_COMMIT();
    for (int ch = 0; ch < 4; ++ch) {
        if (ch + 1 < 4) { prefetch(ch + 1, (ch + 1) & 1); CP_COMMIT(); CP_WAIT1(); }
        else CP_WAIT0();
        __syncthreads();
        mma_phase_nn(sb + (ch & 1) * STG2, a_base, b_base, acc);
        __syncthreads();
    }

    const float SC = 0.08838834764831845f;   // 1/sqrt(128)
    float* ab = att + sel * ATT_N + (size_t)(n * NHD + h) * 512 * 512;
#pragma unroll
    for (int mt = 0; mt < 4; ++mt) {
        int m = cq0 + warp_m * 64 + mt * 16 + (lid >> 2);
#pragma unroll
        for (int nt = 0; nt < 4; ++nt) {
            int sc = ck0 + warp_n * 32 + nt * 8 + (lid & 3) * 2;
            *(float2*)(ab + (size_t)m * 512 + sc) =
                make_float2(acc[mt][nt][0] * SC, acc[mt][nt][1] * SC);
            *(float2*)(ab + (size_t)(m + 8) * 512 + sc) =
                make_float2(acc[mt][nt][2] * SC, acc[mt][nt][3] * SC);
        }
    }
}

// ========== AV with fused softmax (bit-identical to old softmax+av) =========
// grid (4 cq, 64). Pass 1: per-row max & 1/sum (same reduction order as the
// old softmax kernel). Pass 2: A = fp16(exp(att-m)*inv) staged via STS,
// V via register prefetch; same mma_phase_nt; same epilogue.
__global__ __launch_bounds__(256, 2)
void av_fused_kernel(const float* __restrict__ att, const fp16* __restrict__ qk1,
                     fp16* __restrict__ y1) {
    extern __shared__ unsigned char dsm[];
    const uint32_t sb = smem_u32(dsm);
    float* sm_m   = (float*)(dsm + 2 * STGN);
    float* sm_inv = sm_m + 128;
    const size_t QKV_N = (size_t)NB * CCH * HW;
    const size_t ATT_N = (size_t)NB * NHD * 512 * 512;

    int tid = threadIdx.x, wid = tid >> 5, lid = tid & 31;
    int warp_m = wid >> 2, warp_n = wid & 3;
    int z = blockIdx.y, sel = z >> 5, nh = z & 31;
    int n = nh >> 3, h = nh & 7;
    int cq0 = blockIdx.x * 128;
    const float* ab = att + (size_t)sel * ATT_N + (size_t)(n * NHD + h) * 512 * 512;
    size_t vbo = (size_t)n * (CCH * HW) + h * DHEAD;
    const fp16* vb = qk1 + (sel ? 5 : 2) * QKV_N + vbo;

    // ---- pass 1: row max & inverse sum (order matches old softmax kernel) --
    for (int it = 0; it < 16; ++it) {
        int r = it * 8 + wid;
        const float* p = ab + (size_t)(cq0 + r) * 512;
        float v[16];
        float mx = -1e30f;
#pragma unroll
        for (int i = 0; i < 16; ++i) { v[i] = p[lid + i * 32]; mx = fmaxf(mx, v[i]); }
#pragma unroll
        for (int o = 16; o; o >>= 1) mx = fmaxf(mx, __shfl_xor_sync(0xffffffffu, mx, o));
        float s = 0.f;
#pragma unroll
        for (int i = 0; i < 16; ++i) { v[i] = __expf(v[i] - mx); s += v[i]; }
#pragma unroll
        for (int o = 16; o; o >>= 1) s += __shfl_xor_sync(0xffffffffu, s, o);
        if (lid == 0) { sm_m[r] = mx; sm_inv[r] = 1.f / s; }
    }
    __syncthreads();

    float acc[4][4][4];
#pragma unroll
    for (int mt = 0; mt < 4; ++mt)
#pragma unroll
        for (int nt = 0; nt < 4; ++nt)
#pragma unroll
            for (int kk = 0; kk < 4; ++kk) acc[mt][nt][kk] = 0.f;

    int grp = lid >> 3, lr = lid & 7;
    uint32_t a_base = (uint32_t)((warp_m * 64 + (grp & 1) * 8 + lr) * ROWB + (grp >> 1) * 16);
    int l16 = lid & 15;
    uint32_t bt_base = (uint32_t)(l16 * ROW2 + warp_n * 64);

    int row = tid >> 1, half = tid & 1;
    uint32_t dstA = (uint32_t)(row * ROWB + half * 32);
    int ckr = tid >> 3, seg = tid & 7;
    uint32_t dstB = (uint32_t)(ckr * ROW2 + seg * 32);

    float mr = sm_m[row], ir = sm_inv[row];
    const float* arow = ab + (size_t)(cq0 + row) * 512 + half * 16;

    float4 va[4];
    uint4  vv[2];
    auto ldstage = [&](int ch) {
        int ci0 = ch << 5;
        const float* s = arow + ci0;
#pragma unroll
        for (int j = 0; j < 4; ++j) va[j] = *(const float4*)(s + 4 * j);
        const fp16* vp = vb + (size_t)(ci0 + ckr) * HW + seg * 16;
        vv[0] = *(const uint4*)vp;
        vv[1] = *(const uint4*)(vp + 8);
    };

    ldstage(0);
    for (int ch = 0; ch < 16; ++ch) {
        uint32_t s0b = sb + (ch & 1) * STGN;
        // A: P = fp16(exp(att - m) * inv)  (same values the old a1 held)
        uint32_t u[8];
#pragma unroll
        for (int j = 0; j < 4; ++j) {
            __half2 h0 = __floats2half2_rn(__expf(va[j].x - mr) * ir,
                                           __expf(va[j].y - mr) * ir);
            __half2 h1 = __floats2half2_rn(__expf(va[j].z - mr) * ir,
                                           __expf(va[j].w - mr) * ir);
            u[2 * j]     = *(uint32_t*)&h0;
            u[2 * j + 1] = *(uint32_t*)&h1;
        }
        STS128I(s0b + dstA,      u[0], u[1], u[2], u[3]);
        STS128I(s0b + dstA + 16, u[4], u[5], u[6], u[7]);
        // V
        STS128I(s0b + MATB + dstB,      vv[0].x, vv[0].y, vv[0].z, vv[0].w);
        STS128I(s0b + MATB + dstB + 16, vv[1].x, vv[1].y, vv[1].z, vv[1].w);
        __syncthreads();
        if (ch + 1 < 16) ldstage(ch + 1);
        mma_phase_nt(s0b, a_base, bt_base, acc);
        __syncthreads();
    }

    fp16* yb = y1 + (sel ? QKV_N : 0) + vbo;
#pragma unroll
    for (int mt = 0; mt < 4; ++mt) {
        int m = cq0 + warp_m * 64 + mt * 16 + (lid >> 2);
#pragma unroll
        for (int nt = 0; nt < 4; ++nt) {
            int dc = warp_n * 32 + nt * 8 + (lid & 3) * 2;
            __half2 p0 = __floats2half2_rn(acc[mt][nt][0], acc[mt][nt][1]);
            __half2 p1 = __floats2half2_rn(acc[mt][nt][2], acc[mt][nt][3]);
            *(uint32_t*)&yb[(size_t)m * HW + dc] = *(uint32_t*)&p0;
            *(uint32_t*)&yb[(size_t)(m + 8) * HW + dc] = *(uint32_t*)&p1;
        }
    }
}

// ========= 1x1 proj + residual: single fp16, 2-stage (B trans) ==============
__global__ __launch_bounds__(256, 2)
void proj_mma_kernel(const fp16* __restrict__ y1, const fp16* __restrict__ wp1,
                     const float* __restrict__ x_l, const float* __restrict__ x_g,
                     const float* __restrict__ rwp, float* __restrict__ out) {
    extern __shared__ unsigned char dsm[];
    const uint32_t sb = smem_u32(dsm);
    const size_t QKV_N = (size_t)NB * CCH * HW;

    int tid = threadIdx.x, wid = tid >> 5, lid = tid & 31;
    int warp_m = wid >> 2, warp_n = wid & 3;
    int z = blockIdx.z, sel = z >> 2, n = z & 3;
    int sp0 = blockIdx.x * 128, co0 = blockIdx.y * 128;
    const fp16* yb = y1 + (sel ? 0 : QKV_N) + (size_t)n * (CCH * HW);
    const fp16* wb = wp1 + (size_t)sel * 512 * 512;
    const float* xres = sel ? x_g : x_l;
    float* outb = out + (size_t)sel * QKV_N;

    float acc[4][4][4];
#pragma unroll
    for (int mt = 0; mt < 4; ++mt)
#pragma unroll
        for (int nt = 0; nt < 4; ++nt)
#pragma unroll
            for (int kk = 0; kk < 4; ++kk) acc[mt][nt][kk] = 0.f;

    int grp = lid >> 3, lr = lid & 7;
    uint32_t a_base = (uint32_t)((warp_m * 64 + (grp & 1) * 8 + lr) * ROWB + (grp >> 1) * 16);
    int l16 = lid & 15;
    uint32_t bt_base = (uint32_t)(l16 * ROW2 + warp_n * 64);

    int row = tid >> 1, half = tid & 1;
    uint32_t dstA = (uint32_t)(row * ROWB + half * 32);
    int cir = tid >> 3, seg = tid & 7;
    uint32_t dstB = (uint32_t)(cir * ROW2 + seg * 32);

    auto prefetch = [&](int ch, int st) {
        uint32_t s0b = sb + st * STGN;
        int ci0 = ch << 5;
        size_t wof = (size_t)(co0 + row) * 512 + ci0 + half * 16;
        uint32_t da = s0b + dstA;
        CPA(da,      wb + wof,     16u);
        CPA(da + 16, wb + wof + 8, 16u);
        size_t yof = (size_t)(ci0 + cir) * HW + sp0 + seg * 16;
        uint32_t db = s0b + MATB + dstB;
        CPA(db,      yb + yof,     16u);
        CPA(db + 16, yb + yof + 8, 16u);
    };

    prefetch(0, 0); CP_COMMIT();
    for (int ch = 0; ch < 16; ++ch) {
        if (ch + 1 < 16) { prefetch(ch + 1, (ch + 1) & 1); CP_COMMIT(); CP_WAIT1(); }
        else CP_WAIT0();
        __syncthreads();
        mma_phase_nt(sb + (ch & 1) * STGN, a_base, bt_base, acc);
        __syncthreads();
    }

    float rw = *rwp;
#pragma unroll
    for (int mt = 0; mt < 4; ++mt) {
        int m = co0 + warp_m * 64 + mt * 16 + (lid >> 2);
#pragma unroll
        for (int nt = 0; nt < 4; ++nt) {
            int sc = sp0 + warp_n * 32 + nt * 8 + (lid & 3) * 2;
            size_t b0 = ((size_t)n * CCH + m) * HW + sc;
            size_t b1 = ((size_t)n * CCH + m + 8) * HW + sc;
            float2 x0 = *(const float2*)(xres + b0);
            float2 x1 = *(const float2*)(xres + b1);
            *(float2*)(outb + b0) = make_float2(x0.x + rw * acc[mt][nt][0],
                                                x0.y + rw * acc[mt][nt][1]);
            *(float2*)(outb + b1) = make_float2(x1.x + rw * acc[mt][nt][2],
                                                x1.y + rw * acc[mt][nt][3]);
        }
    }
}

// ------------------------------- launcher -----------------------------------
extern "C" void kernel_launch(void* const* d_in, const int* in_sizes, int n_in,
                              void* d_out, int out_size) {
    (void)in_sizes; (void)n_in; (void)out_size;
    const float* x_l = (const float*)d_in[0];
    const float* x_g = (const float*)d_in[1];
    const float* Wp1 = (const float*)d_in[8];
    const float* Wp2 = (const float*)d_in[9];
    const float* rw  = (const float*)d_in[10];
    float* out = (float*)d_out;

    void* p;
    cudaGetSymbolAddress(&p, g_U);   fp16* U   = (fp16*)p;
    cudaGetSymbolAddress(&p, g_V);   fp16* V   = (fp16*)p;
    cudaGetSymbolAddress(&p, g_C);   fp16* C   = (fp16*)p;
    cudaGetSymbolAddress(&p, g_q1);  fp16* q1  = (fp16*)p;
    cudaGetSymbolAddress(&p, g_att); float* attp = (float*)p;
    cudaGetSymbolAddress(&p, g_y1);  fp16* y1  = (fp16*)p;
    cudaGetSymbolAddress(&p, g_wp1); fp16* wp1 = (fp16*)p;

    cudaFuncSetAttribute(wino_gemm,       cudaFuncAttributeMaxDynamicSharedMemorySize, SMN);
    cudaFuncSetAttribute(qk_mma_kernel,   cudaFuncAttributeMaxDynamicSharedMemorySize, SM22);
    cudaFuncSetAttribute(av_fused_kernel, cudaFuncAttributeMaxDynamicSharedMemorySize, SMAV);
    cudaFuncSetAttribute(proj_mma_kernel, cudaFuncAttributeMaxDynamicSharedMemorySize, SMN);

    wino_w<<<dim3(1024, 6), 256>>>(
        (const float*)d_in[2], (const float*)d_in[3], (const float*)d_in[4],
        (const float*)d_in[5], (const float*)d_in[6], (const float*)d_in[7], U);
    wino_v<<<dim3(128, 8), 256>>>(x_l, x_g, V);
    prep_wp<<<dim3(1024, 2), 256>>>(Wp1, Wp2, wp1);

    wino_gemm<<<dim3(2, 4, 216), 256, SMN>>>(U, V, C);
    wino_inv<<<dim3(128, 4, 6), 256>>>(C, q1);

    qk_mma_kernel<<<dim3(4, 4, 64), 256, SM22>>>(q1, attp);

    av_fused_kernel<<<dim3(4, 64), 256, SMAV>>>(attp, q1, y1);

    proj_mma_kernel<<<dim3(8, 4, 8), 256, SMN>>>(y1, wp1, x_l, x_g, rw, out);
}